// round 10
// baseline (speedup 1.0000x reference)
#include <cuda_runtime.h>
#include <cuda_bf16.h>

// Problem constants: im1, im2 are [16, 3, 512, 512] float32.
#define NUM_BINS   256
#define BATCH      16
#define PER_BATCH  (3 * 512 * 512)          // 786432 elements per batch item
#define VEC_PER_BATCH (PER_BATCH / 4)       // 196608 float4 per batch item
#define BPB        37                       // blocks per batch item
#define VEC_PER_BLOCK 5314                  // ceil(196608/37), last block short
#define THREADS    512                      // 16 warps
#define GRID       (BATCH * BPB)            // 592 = 148 SMs x 4 CTAs exactly

// Per-batch histograms for both images, accumulated via L2 atomics.
// g_hist[b*512 + bin] = im1 hist of batch b; +256 = im2 hist.
// Zeroed by each batch's finishing CTA after consumption (replay-safe).
__device__ unsigned int g_hist[BATCH * 2 * NUM_BINS];
__device__ unsigned int g_done_batch[BATCH];
__device__ unsigned int g_done;
__device__ unsigned long long g_total;

__device__ __forceinline__ int bin_of(float v) {
    // Exactly mirrors reference fp32 sequence: floor((v*255) * (256/255)).
    // v >= 0 so only the upper clamp is needed.
    float x = v * 255.0f;
    int i = __float2int_rd(x * (256.0f / 255.0f));
    return i > 255 ? 255 : i;
}

__device__ __forceinline__ uint4 ldcg4(const unsigned int* p) {
    return __ldcg((const uint4*)p);
}

__device__ __forceinline__ void bump8(unsigned int* hl, float4 a, float4 c) {
    atomicAdd(&hl[bin_of(a.x) * 32], 1u);
    atomicAdd(&hl[bin_of(a.y) * 32], 1u);
    atomicAdd(&hl[bin_of(a.z) * 32], 1u);
    atomicAdd(&hl[bin_of(a.w) * 32], 1u);
    atomicAdd(&hl[bin_of(c.x) * 32], 65536u);
    atomicAdd(&hl[bin_of(c.y) * 32], 65536u);
    atomicAdd(&hl[bin_of(c.z) * 32], 65536u);
    atomicAdd(&hl[bin_of(c.w) * 32], 65536u);
}

__global__ __launch_bounds__(THREADS, 4)
void fused_k(const float4* __restrict__ im1,
             const float4* __restrict__ im2,
             float* __restrict__ out) {
    // Lane-private packed counters: sh[bin*32 + lane].
    //   low 16 bits  = im1 count, high 16 bits = im2 count (+65536).
    // Bank of every atomic == lane -> zero conflicts, zero retries.
    __shared__ unsigned int sh[NUM_BINS * 32];   // 32 KB
    __shared__ bool is_batch_last;

    const int b    = blockIdx.x / BPB;
    const int blk  = blockIdx.x - b * BPB;
    const int tid  = threadIdx.x;
    const int lane = tid & 31;

    #pragma unroll
    for (int i = tid; i < NUM_BINS * 32; i += THREADS) sh[i] = 0u;
    __syncthreads();

    unsigned int* hl = &sh[lane];

    // ---- Phase 1: histogram this block's slice of both images ----
    const int start = blk * VEC_PER_BLOCK;
    const int count = (start + VEC_PER_BLOCK <= VEC_PER_BATCH)
                        ? VEC_PER_BLOCK : (VEC_PER_BATCH - start);
    const int base  = b * VEC_PER_BATCH + start;

    int i = tid;
    for (; i + 3 * THREADS < count; i += 4 * THREADS) {
        float4 a0 = __ldcs(&im1[base + i]);
        float4 c0 = __ldcs(&im2[base + i]);
        float4 a1 = __ldcs(&im1[base + i + THREADS]);
        float4 c1 = __ldcs(&im2[base + i + THREADS]);
        float4 a2 = __ldcs(&im1[base + i + 2 * THREADS]);
        float4 c2 = __ldcs(&im2[base + i + 2 * THREADS]);
        float4 a3 = __ldcs(&im1[base + i + 3 * THREADS]);
        float4 c3 = __ldcs(&im2[base + i + 3 * THREADS]);
        bump8(hl, a0, c0);
        bump8(hl, a1, c1);
        bump8(hl, a2, c2);
        bump8(hl, a3, c3);
    }
    for (; i < count; i += THREADS) {
        float4 a0 = __ldcs(&im1[base + i]);
        float4 c0 = __ldcs(&im2[base + i]);
        bump8(hl, a0, c0);
    }
    __syncthreads();

    // Merge lane columns; rotated reads keep banks distinct per warp.
    for (int bin = tid; bin < NUM_BINS; bin += THREADS) {
        unsigned int lo = 0, hi = 0;
        const unsigned int* row = &sh[bin * 32];
        #pragma unroll
        for (int j = 0; j < 32; j++) {
            unsigned int w = row[(bin + j) & 31];
            lo += w & 0xFFFFu;
            hi += w >> 16;
        }
        atomicAdd(&g_hist[b * 2 * NUM_BINS + bin], lo);
        atomicAdd(&g_hist[b * 2 * NUM_BINS + NUM_BINS + bin], hi);
    }

    // ---- Per-batch last-CTA handoff ----
    __threadfence();
    __syncthreads();
    if (tid == 0)
        is_batch_last = (atomicAdd(&g_done_batch[b], 1u) == BPB - 1);
    __syncthreads();
    if (!is_batch_last) return;

    // ---- Phase 2 (last CTA of THIS batch): EMD for batch b ----
    // Warp 0 scans the 256 bins; lane holds 8 consecutive bins.
    if (tid < 32) {
        const unsigned int* hb = &g_hist[b * 2 * NUM_BINS];
        uint4 a0 = ldcg4(hb + lane * 8);
        uint4 a1 = ldcg4(hb + lane * 8 + 4);
        uint4 c0 = ldcg4(hb + NUM_BINS + lane * 8);
        uint4 c1 = ldcg4(hb + NUM_BINS + lane * 8 + 4);

        int d[8];
        d[0] = (int)a0.x - (int)c0.x;  d[1] = (int)a0.y - (int)c0.y;
        d[2] = (int)a0.z - (int)c0.z;  d[3] = (int)a0.w - (int)c0.w;
        d[4] = (int)a1.x - (int)c1.x;  d[5] = (int)a1.y - (int)c1.y;
        d[6] = (int)a1.z - (int)c1.z;  d[7] = (int)a1.w - (int)c1.w;

        #pragma unroll
        for (int j = 1; j < 8; j++) d[j] += d[j - 1];

        int inc = d[7];
        #pragma unroll
        for (int off = 1; off < 32; off <<= 1) {
            int v = __shfl_up_sync(0xffffffffu, inc, off);
            if (lane >= off) inc += v;
        }
        const int ex = inc - d[7];

        long long acc = 0;
        #pragma unroll
        for (int j = 0; j < 8; j++) {
            int c = d[j] + ex;                 // integer cumsum = N * normalized
            acc += (c < 0) ? (long long)(-c) : (long long)c;
        }
        #pragma unroll
        for (int off = 16; off > 0; off >>= 1)
            acc += __shfl_down_sync(0xffffffffu, acc, off);
        if (lane == 0) {
            atomicAdd(&g_total, (unsigned long long)acc);
            g_done_batch[b] = 0u;              // reset for next replay
        }
    }
    __syncthreads();   // warp 0's reads of g_hist[b] complete before zeroing

    // Zero this batch's histogram slice for the next replay.
    for (int j = tid; j < 2 * NUM_BINS; j += THREADS)
        g_hist[b * 2 * NUM_BINS + j] = 0u;

    __threadfence();
    __syncthreads();

    // ---- Global last-batch: emit the scalar ----
    if (tid == 0) {
        if (atomicAdd(&g_done, 1u) == BATCH - 1) {
            unsigned long long t = atomicExch(&g_total, 0ULL);
            // total = (sum_b acc_b / N) / 256 / 3
            double total = (double)t / (double)PER_BATCH / (double)NUM_BINS / 3.0;
            out[0] = (float)total;
            g_done = 0u;
        }
    }
}

extern "C" void kernel_launch(void* const* d_in, const int* in_sizes, int n_in,
                              void* d_out, int out_size) {
    const float4* im1 = (const float4*)d_in[0];
    const float4* im2 = (const float4*)d_in[1];
    float* out = (float*)d_out;

    fused_k<<<GRID, THREADS>>>(im1, im2, out);
}

// round 11
// speedup vs baseline: 1.3249x; 1.3249x over previous
#include <cuda_runtime.h>
#include <cuda_bf16.h>

// Problem constants: im1, im2 are [16, 3, 512, 512] float32.
#define NUM_BINS   256
#define BATCH      16
#define PER_BATCH  (3 * 512 * 512)          // 786432 elements per batch item
#define VEC_PER_BATCH (PER_BATCH / 4)       // 196608 float4 per batch item
#define BPB        37                       // blocks per batch item
#define VEC_PER_BLOCK 5314                  // ceil(196608/37), last block short
#define THREADS    512                      // 16 warps
#define GRID       (BATCH * BPB)            // 592 = 148 SMs x 4 CTAs exactly

// Per-batch histograms for both images, accumulated via L2 atomics.
// g_hist[b*512 + bin] = im1 hist of batch b; +256 = im2 hist.
// Zero at module load; the finalizing block re-zeroes after consuming.
__device__ unsigned int g_hist[BATCH * 2 * NUM_BINS];
__device__ unsigned int g_done;

__device__ __forceinline__ int bin_of(float v) {
    // Exactly mirrors reference fp32 sequence: floor((v*255) * (256/255)).
    // v >= 0 so only the upper clamp is needed.
    float x = v * 255.0f;
    int i = __float2int_rd(x * (256.0f / 255.0f));
    return i > 255 ? 255 : i;
}

__device__ __forceinline__ uint4 ldcg4(const unsigned int* p) {
    return __ldcg((const uint4*)p);
}

__device__ __forceinline__ void bump8(unsigned int* hl, float4 a, float4 c) {
    atomicAdd(&hl[bin_of(a.x) * 32], 1u);
    atomicAdd(&hl[bin_of(a.y) * 32], 1u);
    atomicAdd(&hl[bin_of(a.z) * 32], 1u);
    atomicAdd(&hl[bin_of(a.w) * 32], 1u);
    atomicAdd(&hl[bin_of(c.x) * 32], 65536u);
    atomicAdd(&hl[bin_of(c.y) * 32], 65536u);
    atomicAdd(&hl[bin_of(c.z) * 32], 65536u);
    atomicAdd(&hl[bin_of(c.w) * 32], 65536u);
}

__global__ __launch_bounds__(THREADS, 4)
void fused_k(const float4* __restrict__ im1,
             const float4* __restrict__ im2,
             float* __restrict__ out) {
    // Lane-private packed counters: sh[bin*32 + lane].
    //   low 16 bits  = im1 count, high 16 bits = im2 count (+65536).
    // Bank of every atomic == lane -> all 32 lanes of a warp hit distinct
    // banks on every ATOMS: zero bank conflicts, zero same-address retries.
    // Max per counter: 16 warps * 11 iters * 4 vals ~ 704 << 65535.
    __shared__ unsigned int sh[NUM_BINS * 32];   // 32 KB
    __shared__ bool is_last;
    __shared__ long long warp_acc[16];

    const int b    = blockIdx.x / BPB;
    const int blk  = blockIdx.x - b * BPB;
    const int tid  = threadIdx.x;
    const int wid  = tid >> 5;
    const int lane = tid & 31;

    // Vectorized zero: 2048 uint4 over 512 threads = 4 iterations.
    {
        uint4* sh4 = reinterpret_cast<uint4*>(sh);
        const uint4 z = make_uint4(0u, 0u, 0u, 0u);
        #pragma unroll
        for (int i = tid; i < NUM_BINS * 8; i += THREADS) sh4[i] = z;
    }
    __syncthreads();

    unsigned int* hl = &sh[lane];

    // ---- Phase 1: histogram this block's slice of both images ----
    const int start = blk * VEC_PER_BLOCK;
    const int count = (start + VEC_PER_BLOCK <= VEC_PER_BATCH)
                        ? VEC_PER_BLOCK : (VEC_PER_BATCH - start);
    const int base  = b * VEC_PER_BATCH + start;

    // Unroll-by-4: all 8 wide loads batched ahead of the 32 atomics (MLP=8).
    int i = tid;
    for (; i + 3 * THREADS < count; i += 4 * THREADS) {
        float4 a0 = __ldcs(&im1[base + i]);
        float4 c0 = __ldcs(&im2[base + i]);
        float4 a1 = __ldcs(&im1[base + i + THREADS]);
        float4 c1 = __ldcs(&im2[base + i + THREADS]);
        float4 a2 = __ldcs(&im1[base + i + 2 * THREADS]);
        float4 c2 = __ldcs(&im2[base + i + 2 * THREADS]);
        float4 a3 = __ldcs(&im1[base + i + 3 * THREADS]);
        float4 c3 = __ldcs(&im2[base + i + 3 * THREADS]);
        bump8(hl, a0, c0);
        bump8(hl, a1, c1);
        bump8(hl, a2, c2);
        bump8(hl, a3, c3);
    }
    for (; i < count; i += THREADS) {
        float4 a0 = __ldcs(&im1[base + i]);
        float4 c0 = __ldcs(&im2[base + i]);
        bump8(hl, a0, c0);
    }
    __syncthreads();

    // Merge lane columns. LDS.128 with quad-rotation (bin+j)&7: lanes within
    // a wavefront hit distinct 4-bank groups -> conflict-free, 8 loads/bin.
    for (int bin = tid; bin < NUM_BINS; bin += THREADS) {
        const uint4* row4 = reinterpret_cast<const uint4*>(&sh[bin * 32]);
        unsigned int lo = 0, hi = 0;
        #pragma unroll
        for (int j = 0; j < 8; j++) {
            uint4 w = row4[(bin + j) & 7];
            lo += (w.x & 0xFFFFu) + (w.y & 0xFFFFu) + (w.z & 0xFFFFu) + (w.w & 0xFFFFu);
            hi += (w.x >> 16) + (w.y >> 16) + (w.z >> 16) + (w.w >> 16);
        }
        atomicAdd(&g_hist[b * 2 * NUM_BINS + bin], lo);
        atomicAdd(&g_hist[b * 2 * NUM_BINS + NUM_BINS + bin], hi);
    }

    // ---- Last-block-done handoff ----
    __threadfence();
    __syncthreads();
    if (tid == 0) is_last = (atomicAdd(&g_done, 1u) == GRID - 1);
    __syncthreads();
    if (!is_last) return;

    // ---- Phase 2 (one block): EMD finalization, barrier-free scans ----
    // Warp w handles batch w (16 warps, 16 batches). Lane holds 8 bins.
    long long acc = 0;
    {
        const unsigned int* hb = &g_hist[wid * 2 * NUM_BINS];

        uint4 a0 = ldcg4(hb + lane * 8);
        uint4 a1 = ldcg4(hb + lane * 8 + 4);
        uint4 c0 = ldcg4(hb + NUM_BINS + lane * 8);
        uint4 c1 = ldcg4(hb + NUM_BINS + lane * 8 + 4);

        int d[8];
        d[0] = (int)a0.x - (int)c0.x;  d[1] = (int)a0.y - (int)c0.y;
        d[2] = (int)a0.z - (int)c0.z;  d[3] = (int)a0.w - (int)c0.w;
        d[4] = (int)a1.x - (int)c1.x;  d[5] = (int)a1.y - (int)c1.y;
        d[6] = (int)a1.z - (int)c1.z;  d[7] = (int)a1.w - (int)c1.w;

        // In-lane sequential inclusive prefix over 8 bins.
        #pragma unroll
        for (int j = 1; j < 8; j++) d[j] += d[j - 1];

        // Warp-wide exclusive scan of lane totals (5 shuffles).
        int inc = d[7];
        #pragma unroll
        for (int off = 1; off < 32; off <<= 1) {
            int v = __shfl_up_sync(0xffffffffu, inc, off);
            if (lane >= off) inc += v;
        }
        const int ex = inc - d[7];

        #pragma unroll
        for (int j = 0; j < 8; j++) {
            int c = d[j] + ex;                 // integer cumsum = N * normalized
            acc += (c < 0) ? (long long)(-c) : (long long)c;
        }
    }

    // Reduce across lanes, then across the 16 warps.
    #pragma unroll
    for (int off = 16; off > 0; off >>= 1)
        acc += __shfl_down_sync(0xffffffffu, acc, off);
    if (lane == 0) warp_acc[wid] = acc;
    __syncthreads();

    if (tid == 0) {
        long long total_i = 0;
        #pragma unroll
        for (int w = 0; w < 16; w++) total_i += warp_acc[w];
        // total = (sum_b acc_b / N) / 256 / 3
        double total = (double)total_i / (double)PER_BATCH / (double)NUM_BINS / 3.0;
        out[0] = (float)total;
    }
    __syncthreads();

    // Restore zero-invariant for next graph replay.
    for (int j = tid; j < BATCH * 2 * NUM_BINS; j += THREADS) g_hist[j] = 0u;
    if (tid == 0) g_done = 0u;
}

extern "C" void kernel_launch(void* const* d_in, const int* in_sizes, int n_in,
                              void* d_out, int out_size) {
    const float4* im1 = (const float4*)d_in[0];
    const float4* im2 = (const float4*)d_in[1];
    float* out = (float*)d_out;

    fused_k<<<GRID, THREADS>>>(im1, im2, out);
}